// round 3
// baseline (speedup 1.0000x reference)
#include <cuda_runtime.h>
#include <stdint.h>
#include <math.h>

// Problem dims (dataset): N=100000 nodes, C=32 classes, E=3.2M edges
#define NMAX 100000
#define CC 32

// Scratch (device globals; no allocation allowed)
__device__ float g_p[NMAX * CC];      // masked softmax probs (12.8MB)
__device__ float g_s[NMAX * CC];      // scatter matrix s[c][a] (12.8MB)
__device__ int2  g_info[NMAX];        // .x = bitcast(dinv), .y = label (-1 unmasked)
__device__ float g_deg[NMAX];
__device__ float g_H[CC * CC];
__device__ float g_cnt[CC];
__device__ int   g_maskmode;          // 0=uint8, 1=float32, 2=int32

__device__ __forceinline__ bool get_mask(const void* m, int r, int mm) {
    if (mm == 0) return ((const uint8_t*)m)[r] != 0;
    if (mm == 2) return ((const int*)m)[r] != 0;
    return ((const float*)m)[r] != 0.0f;
}

// ---------------------------------------------------------------------------
// deg init = 1.0 (self-loop weight), zero H/cnt, detect mask dtype.
__global__ void zero_detect_kernel(const void* mask, int n) {
    int i = blockIdx.x * blockDim.x + threadIdx.x;
    if (i < n) g_deg[i] = 1.0f;
    if (i < CC * CC) g_H[i] = 0.0f;
    if (i < CC) g_cnt[i] = 0.0f;
    if (i == 0) {
        const int*   mi = (const int*)mask;
        const float* mf = (const float*)mask;
        bool isInt = true, isFloat = true;
        for (int k = 0; k < 64; k++) {
            int v = mi[k];
            if (v != 0 && v != 1) isInt = false;
            float f = mf[k];
            if (f != 0.0f && f != 1.0f) isFloat = false;
        }
        g_maskmode = isInt ? 2 : (isFloat ? 1 : 0);
    }
}

// deg += segment_sum(w, row); vectorized 4 edges/thread.
__global__ void deg_kernel(const int* __restrict__ row,
                           const float* __restrict__ w, int E) {
    int base = (blockIdx.x * blockDim.x + threadIdx.x) * 4;
    if (base + 3 < E) {
        int4   r4 = *(const int4*)(row + base);
        float4 w4 = *(const float4*)(w + base);
        atomicAdd(&g_deg[r4.x], w4.x);
        atomicAdd(&g_deg[r4.y], w4.y);
        atomicAdd(&g_deg[r4.z], w4.z);
        atomicAdd(&g_deg[r4.w], w4.w);
    } else {
        for (int e = base; e < E; e++) atomicAdd(&g_deg[row[e]], w[e]);
    }
}

// 4 threads/node: softmax -> mask-replace by y; also writes this node's s-row
// (one-hot dinv^2 on masked nodes = the self-loop contribution; zeros else).
__global__ void node_kernel(const float* __restrict__ inp,
                            const float* __restrict__ y,
                            const void* mask, int N) {
    int tid  = blockIdx.x * blockDim.x + threadIdx.x;
    int node = tid >> 2;
    int sub  = tid & 3;
    if (node >= N) return;
    int mm = g_maskmode;

    const float4* ip = (const float4*)(inp + node * CC) + sub * 2;
    float4 a = ip[0], b = ip[1];

    float mx = fmaxf(fmaxf(fmaxf(a.x, a.y), fmaxf(a.z, a.w)),
                     fmaxf(fmaxf(b.x, b.y), fmaxf(b.z, b.w)));
    mx = fmaxf(mx, __shfl_xor_sync(0xffffffffu, mx, 1));
    mx = fmaxf(mx, __shfl_xor_sync(0xffffffffu, mx, 2));

    float e0 = __expf(a.x - mx), e1 = __expf(a.y - mx),
          e2 = __expf(a.z - mx), e3 = __expf(a.w - mx),
          e4 = __expf(b.x - mx), e5 = __expf(b.y - mx),
          e6 = __expf(b.z - mx), e7 = __expf(b.w - mx);
    float s = ((e0 + e1) + (e2 + e3)) + ((e4 + e5) + (e6 + e7));
    s += __shfl_xor_sync(0xffffffffu, s, 1);
    s += __shfl_xor_sync(0xffffffffu, s, 2);
    float inv = __frcp_rn(s);

    const float4* yp = (const float4*)(y + node * CC) + sub * 2;
    float4 ya = yp[0], yb = yp[1];

    bool mk = get_mask(mask, node, mm);
    float4 pa, pb;
    int labl = -1;
    if (mk) {
        pa = ya; pb = yb;
        int bse = sub * 8;
        if (ya.x > 0.5f) labl = bse + 0;
        if (ya.y > 0.5f) labl = bse + 1;
        if (ya.z > 0.5f) labl = bse + 2;
        if (ya.w > 0.5f) labl = bse + 3;
        if (yb.x > 0.5f) labl = bse + 4;
        if (yb.y > 0.5f) labl = bse + 5;
        if (yb.z > 0.5f) labl = bse + 6;
        if (yb.w > 0.5f) labl = bse + 7;
    } else {
        pa = make_float4(e0 * inv, e1 * inv, e2 * inv, e3 * inv);
        pb = make_float4(e4 * inv, e5 * inv, e6 * inv, e7 * inv);
    }
    labl = max(labl, __shfl_xor_sync(0xffffffffu, labl, 1));
    labl = max(labl, __shfl_xor_sync(0xffffffffu, labl, 2));

    float4* op = (float4*)(g_p + node * CC) + sub * 2;
    op[0] = pa; op[1] = pb;

    // s row: self-loop contribution dinv^2 at [node][labl] if masked, else 0
    float d  = g_deg[node];
    float di = rsqrtf(d);       // deg >= 1 always (self-loop)
    float dsq = di * di;
    float4 sa = make_float4(0.f, 0.f, 0.f, 0.f), sb = sa;
    if (mk) {
        int bse = sub * 8;
        if (labl == bse + 0) sa.x = dsq;
        if (labl == bse + 1) sa.y = dsq;
        if (labl == bse + 2) sa.z = dsq;
        if (labl == bse + 3) sa.w = dsq;
        if (labl == bse + 4) sb.x = dsq;
        if (labl == bse + 5) sb.y = dsq;
        if (labl == bse + 6) sb.z = dsq;
        if (labl == bse + 7) sb.w = dsq;
    }
    float4* sp = (float4*)(g_s + node * CC) + sub * 2;
    sp[0] = sa; sp[1] = sb;

    if (sub == 0) {
        g_info[node] = make_int2(__float_as_int(di), mk ? labl : -1);
        if (mk) atomicAdd(&g_cnt[labl], 1.0f);
    }
}

// Edge scatter: masked-row edges -> s[col][label_row] += dinv_r * w * dinv_c.
// Pure gather+atomic, no warp serialization. 4 edges/thread for MLP.
__global__ void scatter_kernel(const int* __restrict__ row,
                               const int* __restrict__ col,
                               const float* __restrict__ w, int E) {
    int base = (blockIdx.x * blockDim.x + threadIdx.x) * 4;
    if (base + 3 < E) {
        int4   r4 = *(const int4*)(row + base);
        int4   c4 = *(const int4*)(col + base);
        float4 w4 = *(const float4*)(w + base);
        int2 i0 = g_info[r4.x];
        int2 i1 = g_info[r4.y];
        int2 i2 = g_info[r4.z];
        int2 i3 = g_info[r4.w];
        const int* inf = (const int*)g_info;
        if (i0.y >= 0) {
            float dc = __int_as_float(inf[c4.x * 2]);
            atomicAdd(&g_s[c4.x * CC + i0.y], __int_as_float(i0.x) * w4.x * dc);
        }
        if (i1.y >= 0) {
            float dc = __int_as_float(inf[c4.y * 2]);
            atomicAdd(&g_s[c4.y * CC + i1.y], __int_as_float(i1.x) * w4.y * dc);
        }
        if (i2.y >= 0) {
            float dc = __int_as_float(inf[c4.z * 2]);
            atomicAdd(&g_s[c4.z * CC + i2.y], __int_as_float(i2.x) * w4.z * dc);
        }
        if (i3.y >= 0) {
            float dc = __int_as_float(inf[c4.w * 2]);
            atomicAdd(&g_s[c4.w * CC + i3.y], __int_as_float(i3.x) * w4.w * dc);
        }
    } else {
        const int* inf = (const int*)g_info;
        for (int e = base; e < E; e++) {
            int r = row[e], c = col[e];
            int2 ir = g_info[r];
            if (ir.y >= 0) {
                float dc = __int_as_float(inf[c * 2]);
                atomicAdd(&g_s[c * CC + ir.y],
                          __int_as_float(ir.x) * w[e] * dc);
            }
        }
    }
}

// Dense rank-1 sum: H[a][j] = sum_c s[c][a] * p[c][j]. One warp per node
// (grid-strided); lane j keeps H[*][j] column in 32 registers.
__global__ void dense_kernel(int N) {
    int wid  = threadIdx.x >> 5;
    int lane = threadIdx.x & 31;
    int gw     = blockIdx.x * 8 + wid;
    int stride = gridDim.x * 8;

    float acc[CC];
    #pragma unroll
    for (int a = 0; a < CC; a++) acc[a] = 0.0f;

    for (int c = gw; c < N; c += stride) {
        float sv = g_s[c * CC + lane];
        if (__ballot_sync(0xffffffffu, sv != 0.0f) == 0) continue;
        float pv = g_p[c * CC + lane];
        #pragma unroll
        for (int a = 0; a < CC; a++)
            acc[a] += __shfl_sync(0xffffffffu, sv, a) * pv;
    }
    #pragma unroll
    for (int a = 0; a < CC; a++)
        atomicAdd(&g_H[a * CC + lane], acc[a]);
}

// Final: H = acc/cnt, NaN fixups, Sinkhorn to convergence (fixed point of the
// reference's 3000 iterations).
__global__ void final_kernel(float* __restrict__ out) {
    __shared__ float sm[CC * 33];
    __shared__ float sred[CC];
    __shared__ int   sflag;

    int i = threadIdx.x >> 5;   // row
    int j = threadIdx.x & 31;   // col (lane)

    float h = g_H[i * CC + j] / g_cnt[i];   // 0/0 -> NaN if empty class

    // Fixup 1: H = where(isnan(H), H^T, H)
    sm[j * 33 + i] = h;
    __syncthreads();
    float ht = sm[i * 33 + j];
    if (isnan(h)) h = ht;
    __syncthreads();

    // Fixup 2
    bool n2 = isnan(h);
    float h0 = n2 ? 0.0f : h;
    float rs = h0;
    float rn = n2 ? 1.0f : 0.0f;
    #pragma unroll
    for (int o = 16; o; o >>= 1) {
        rs += __shfl_xor_sync(0xffffffffu, rs, o);
        rn += __shfl_xor_sync(0xffffffffu, rn, o);
    }
    float miss = (1.0f - rs) / rn;
    h = n2 ? miss : h0;

    // Sinkhorn: col-normalize then row-normalize until converged (cap 3000)
    float hsave = h;
    for (int it = 0; it < 3000; it++) {
        sm[i * 33 + j] = h;
        __syncthreads();
        float vc = sm[j * 33 + i];
        float cs = vc;
        #pragma unroll
        for (int o = 16; o; o >>= 1) cs += __shfl_xor_sync(0xffffffffu, cs, o);
        vc /= cs;
        sm[j * 33 + i] = vc;
        __syncthreads();
        h = sm[i * 33 + j];
        float rs2 = h;
        #pragma unroll
        for (int o = 16; o; o >>= 1) rs2 += __shfl_xor_sync(0xffffffffu, rs2, o);
        h /= rs2;

        if ((it & 7) == 7) {
            float d = fabsf(h - hsave);
            #pragma unroll
            for (int o = 16; o; o >>= 1) d = fmaxf(d, __shfl_xor_sync(0xffffffffu, d, o));
            if (j == 0) sred[i] = d;
            __syncthreads();
            if (threadIdx.x == 0) {
                float m = 0.0f;
                for (int k = 0; k < CC; k++) m = fmaxf(m, sred[k]);
                sflag = (m < 1e-8f) ? 1 : 0;
            }
            __syncthreads();
            if (sflag) break;
            hsave = h;
        }
    }
    out[i * CC + j] = h;
}

// ---------------------------------------------------------------------------
extern "C" void kernel_launch(void* const* d_in, const int* in_sizes, int n_in,
                              void* d_out, int out_size) {
    const int*   ei   = (const int*)d_in[0];    // edge_index (2,E)
    const float* ew   = (const float*)d_in[1];  // edge_weight (E,)
    const float* inp  = (const float*)d_in[2];  // inputs (N,32)
    const float* y    = (const float*)d_in[3];  // y (N,32)
    const void*  mask = d_in[4];                // sample_mask (N,)

    int E = in_sizes[1];
    int N = in_sizes[2] / CC;
    const int* rowp = ei;
    const int* colp = ei + E;

    int eb = (E / 4 + 255) / 256 + 1;   // covers vec body + scalar tail

    zero_detect_kernel<<<(N + 255) / 256, 256>>>(mask, N);
    deg_kernel<<<eb, 256>>>(rowp, ew, E);
    node_kernel<<<(N * 4 + 255) / 256, 256>>>(inp, y, mask, N);
    scatter_kernel<<<eb, 256>>>(rowp, colp, ew, E);
    dense_kernel<<<296, 256>>>(N);
    final_kernel<<<1, 1024>>>((float*)d_out);
}